// round 1
// baseline (speedup 1.0000x reference)
#include <cuda_runtime.h>
#include <math.h>

// ---------------- problem constants ----------------
#define BN     8      // batch
#define NN     1024   // seq len
#define DD     512    // model dim
#define HH     8      // heads
#define DHD    64     // dim per head
#define NHASH  4      // hash rounds
#define NBUCK  256    // buckets per round (N / BUCKET)
#define BSZ    4      // bucket size
#define BHN    (BN*HH)        // 64
#define MTOT   (BN*NN)        // 8192 rows for GEMMs
#define CHTOT  (NHASH*NBUCK)  // 1024 chunks per bh (flat, cross-round)

// ---------------- scratch (device globals; no runtime alloc) ----------------
__device__ float g_qk    [BN*NN*DD];          // 16 MB
__device__ float g_v     [BN*NN*DD];          // 16 MB
__device__ int   g_bucket[BHN*NHASH*NN];      // 1 MB
__device__ int   g_st    [BHN*NHASH*NN];      // 1 MB
__device__ float g_o     [(size_t)BHN*NHASH*NN*DHD]; // 64 MB
__device__ float g_logits[BHN*NHASH*NN];      // 1 MB
__device__ float g_att   [BN*NN*DD];          // 16 MB

// ---------------- K1/K6: tiled SGEMM  C[M,N] = A[M,K] @ B[K,N] (+bias) ------
// BM=BN=64, BK=16, 256 threads, 4x4 microtile per thread.
template<bool HASBIAS>
__global__ __launch_bounds__(256) void sgemm_k(
    const float* __restrict__ A, const float* __restrict__ Bm,
    const float* __restrict__ bias, float* __restrict__ C,
    int M, int Nn, int K)
{
    __shared__ float As[16][64];
    __shared__ float Bs[16][64];
    int tid = threadIdx.x;
    int tx = tid & 15, ty = tid >> 4;
    int bm = blockIdx.y * 64, bn = blockIdx.x * 64;
    float acc[4][4] = {};
    int la_m = tid >> 2;         // 0..63
    int la_k = (tid & 3) * 4;    // 0,4,8,12
    int lb_k = tid >> 4;         // 0..15
    int lb_n = (tid & 15) * 4;

    for (int k0 = 0; k0 < K; k0 += 16) {
        float4 av = *(const float4*)(A  + (size_t)(bm + la_m) * K + k0 + la_k);
        float4 bv = *(const float4*)(Bm + (size_t)(k0 + lb_k) * Nn + bn + lb_n);
        As[la_k+0][la_m] = av.x;
        As[la_k+1][la_m] = av.y;
        As[la_k+2][la_m] = av.z;
        As[la_k+3][la_m] = av.w;
        *(float4*)&Bs[lb_k][lb_n] = bv;
        __syncthreads();
        #pragma unroll
        for (int k = 0; k < 16; k++) {
            float4 a4 = *(const float4*)&As[k][ty*4];
            float4 b4 = *(const float4*)&Bs[k][tx*4];
            float aa[4] = {a4.x, a4.y, a4.z, a4.w};
            float bb[4] = {b4.x, b4.y, b4.z, b4.w};
            #pragma unroll
            for (int i = 0; i < 4; i++)
                #pragma unroll
                for (int j = 0; j < 4; j++)
                    acc[i][j] = fmaf(aa[i], bb[j], acc[i][j]);
        }
        __syncthreads();
    }
    #pragma unroll
    for (int i = 0; i < 4; i++) {
        float4 o;
        o.x = acc[i][0]; o.y = acc[i][1]; o.z = acc[i][2]; o.w = acc[i][3];
        if (HASBIAS) {
            o.x += bias[bn + tx*4 + 0];
            o.y += bias[bn + tx*4 + 1];
            o.z += bias[bn + tx*4 + 2];
            o.w += bias[bn + tx*4 + 3];
        }
        *(float4*)(C + (size_t)(bm + ty*4 + i) * Nn + bn + tx*4) = o;
    }
}

// ---------------- K2: LSH hashing: rotated = qk . rot, argmax over [r,-r] ---
// Block: (bh, 32-token tile). 256 threads = 32 tokens x 8 groups (16 i's each).
__global__ __launch_bounds__(256) void hash_kernel(const float* __restrict__ rot)
{
    __shared__ float qs[32][68];
    __shared__ float rs[64][132];
    __shared__ float bvs[32][8];
    __shared__ int   bis[32][8];
    int bh = blockIdx.y;
    int t0 = blockIdx.x * 32;
    int b = bh >> 3, h = bh & 7;
    int tid = threadIdx.x;

    for (int idx = tid; idx < 32*64; idx += 256) {
        int tk = idx >> 6, f = idx & 63;
        qs[tk][f] = g_qk[((size_t)(b*NN + t0 + tk))*DD + h*DHD + f];
    }
    int tk = tid >> 3, g = tid & 7;

    for (int r = 0; r < NHASH; r++) {
        __syncthreads();   // qk ready / previous round done with rs
        for (int idx = tid; idx < 64*128; idx += 256) {
            int f = idx >> 7, i = idx & 127;
            rs[f][i] = rot[f*(NHASH*128) + r*128 + i];
        }
        __syncthreads();

        float acc[16];
        #pragma unroll
        for (int ii = 0; ii < 16; ii++) acc[ii] = 0.f;
        for (int f = 0; f < 64; f++) {
            float q = qs[tk][f];
            const float* rp = &rs[f][g*16];
            #pragma unroll
            for (int ii = 0; ii < 16; ii++)
                acc[ii] = fmaf(q, rp[ii], acc[ii]);
        }
        // first-index-wins argmax over concat([rot, -rot])
        float bv = acc[0]; int bi = g*16;
        #pragma unroll
        for (int ii = 1; ii < 16; ii++)
            if (acc[ii] > bv) { bv = acc[ii]; bi = g*16 + ii; }
        #pragma unroll
        for (int ii = 0; ii < 16; ii++)
            if (-acc[ii] > bv) { bv = -acc[ii]; bi = 128 + g*16 + ii; }
        bvs[tk][g] = bv; bis[tk][g] = bi;
        __syncthreads();
        if (g == 0) {
            float best = bvs[tk][0]; int besti = bis[tk][0];
            #pragma unroll
            for (int gg = 1; gg < 8; gg++) {
                float v = bvs[tk][gg]; int vi = bis[tk][gg];
                if (v > best || (v == best && vi < besti)) { best = v; besti = vi; }
            }
            g_bucket[(bh*NHASH + r)*NN + t0 + tk] = besti;
        }
    }
}

// ---------------- K3: stable counting sort per (bh, round) ------------------
__global__ __launch_bounds__(256) void sort_kernel()
{
    __shared__ int bks[NN];
    __shared__ int hist[NBUCK];
    __shared__ int offs[NBUCK];
    int bhr = blockIdx.x;              // bh*NHASH + r
    int tid = threadIdx.x;
    for (int t = tid; t < NN; t += 256) bks[t] = g_bucket[bhr*NN + t];
    hist[tid] = 0;
    __syncthreads();
    for (int t = tid; t < NN; t += 256) atomicAdd(&hist[bks[t]], 1);
    __syncthreads();
    if (tid == 0) {
        int s = 0;
        for (int bkt = 0; bkt < NBUCK; bkt++) { offs[bkt] = s; s += hist[bkt]; }
    }
    __syncthreads();
    int mybkt = tid;                   // one bucket per thread; stable by position
    int off = offs[mybkt];
    for (int t = 0; t < NN; t++)
        if (bks[t] == mybkt) { g_st[bhr*NN + off] = t; off++; }
}

// ---------------- K4: chunked attention, warp per chunk ---------------------
// look_one_back runs over the FLAT 1024-chunk axis (crosses hash rounds).
__global__ __launch_bounds__(128) void attn_kernel()
{
    __shared__ float qs[4][4][68];
    __shared__ float ks[4][8][68];
    __shared__ float vs[4][8][68];
    __shared__ float ps[4][4][8];
    __shared__ int   tqa[4][4];
    __shared__ int   tka[4][8];
    int w = threadIdx.x >> 5;
    int lane = threadIdx.x & 31;
    int C = blockIdx.x * 4 + w;                 // global (bh, flat chunk)
    int bh = C >> 10;
    int Cl = C & 1023;
    int r = Cl >> 8, c = Cl & 255;
    int Cp = (Cl + 1023) & 1023;                // previous chunk (wraps rounds)
    int rp = Cp >> 8, cp = Cp & 255;
    int b = bh >> 3, h = bh & 7;

    if (lane < 4) {
        int t = g_st[(bh*NHASH + r)*NN + c*BSZ + lane];
        tqa[w][lane] = t;
        tka[w][lane] = t;
        tka[w][lane + 4] = g_st[(bh*NHASH + rp)*NN + cp*BSZ + lane];
    }
    __syncwarp();

    #pragma unroll
    for (int i = 0; i < 4; i++) {
        const float* src = g_qk + ((size_t)(b*NN + tqa[w][i]))*DD + h*DHD;
        qs[w][i][lane]      = src[lane];
        qs[w][i][lane + 32] = src[lane + 32];
    }
    #pragma unroll
    for (int j = 0; j < 8; j++) {
        int t = tka[w][j];
        const float* ksrc = g_qk + ((size_t)(b*NN + t))*DD + h*DHD;
        const float* vsrc = g_v  + ((size_t)(b*NN + t))*DD + h*DHD;
        float k0 = ksrc[lane], k1 = ksrc[lane + 32];
        vs[w][j][lane]      = vsrc[lane];
        vs[w][j][lane + 32] = vsrc[lane + 32];
        float ss = k0*k0 + k1*k1;
        #pragma unroll
        for (int d = 16; d >= 1; d >>= 1) ss += __shfl_xor_sync(0xffffffffu, ss, d);
        float scale = 1.0f / fmaxf(sqrtf(ss), 1e-6f);   // make_unit_length
        ks[w][j][lane]      = k0 * scale;
        ks[w][j][lane + 32] = k1 * scale;
    }
    __syncwarp();

    int i = lane >> 3, j = lane & 7;            // 32 lanes = 4x8 dot products
    float d = 0.f;
    #pragma unroll
    for (int f = 0; f < 64; f++)
        d = fmaf(qs[w][i][f], ks[w][j][f], d);
    d *= 0.125f;                                 // dh^-0.5
    if (tqa[w][i] == tka[w][j]) d = -5e4f;       // self-token mask (by id!)

    float m = d;
    #pragma unroll
    for (int dd = 4; dd >= 1; dd >>= 1) m = fmaxf(m, __shfl_xor_sync(0xffffffffu, m, dd));
    float e = expf(d - m);
    float s = e;
    #pragma unroll
    for (int dd = 4; dd >= 1; dd >>= 1) s += __shfl_xor_sync(0xffffffffu, s, dd);
    float lse = m + logf(s);
    ps[w][i][j] = e / s;
    __syncwarp();

    #pragma unroll
    for (int it = 0; it < 8; it++) {
        int idx = it * 32 + lane;
        int oi = idx >> 6, f = idx & 63;
        float acc = 0.f;
        #pragma unroll
        for (int jj = 0; jj < 8; jj++)
            acc = fmaf(ps[w][oi][jj], vs[w][jj][f], acc);
        // scatter-unsort directly by token id
        g_o[(((size_t)(bh*NHASH + r))*NN + tqa[w][oi])*DHD + f] = acc;
    }
    if (j == 0)
        g_logits[(bh*NHASH + r)*NN + tqa[w][i]] = lse;
}

// ---------------- K5: combine hash rounds + merge heads ---------------------
__global__ __launch_bounds__(256) void combine_kernel()
{
    int bh = blockIdx.y;
    int t = blockIdx.x * 4 + (threadIdx.x >> 6);
    int f = threadIdx.x & 63;
    int b = bh >> 3, h = bh & 7;
    float l[NHASH];
    #pragma unroll
    for (int r = 0; r < NHASH; r++) l[r] = g_logits[(bh*NHASH + r)*NN + t];
    float m = fmaxf(fmaxf(l[0], l[1]), fmaxf(l[2], l[3]));
    float s = 0.f;
    #pragma unroll
    for (int r = 0; r < NHASH; r++) s += expf(l[r] - m);
    float acc = 0.f;
    #pragma unroll
    for (int r = 0; r < NHASH; r++) {
        float wr = expf(l[r] - m) / s;
        acc = fmaf(wr, g_o[(((size_t)(bh*NHASH + r))*NN + t)*DHD + f], acc);
    }
    g_att[((size_t)(b*NN + t))*DD + h*DHD + f] = acc;
}

// ---------------- launch ----------------------------------------------------
extern "C" void kernel_launch(void* const* d_in, const int* in_sizes, int n_in,
                              void* d_out, int out_size)
{
    (void)in_sizes; (void)n_in; (void)out_size;
    const float* queries = (const float*)d_in[0];
    // d_in[1] keys, d_in[2] values, d_in[8] attn_mask: unused by ReformerLayer
    const float* Wqk  = (const float*)d_in[3];
    const float* Wv   = (const float*)d_in[4];
    const float* Wout = (const float*)d_in[5];
    const float* bout = (const float*)d_in[6];
    const float* rot  = (const float*)d_in[7];
    float* out = (float*)d_out;

    float *qk, *v, *att;
    cudaGetSymbolAddress((void**)&qk,  g_qk);
    cudaGetSymbolAddress((void**)&v,   g_v);
    cudaGetSymbolAddress((void**)&att, g_att);

    dim3 ggrid(DD/64, MTOT/64);   // (8, 128)
    sgemm_k<false><<<ggrid, 256>>>(queries, Wqk, nullptr, qk, MTOT, DD, DD);
    sgemm_k<false><<<ggrid, 256>>>(queries, Wv,  nullptr, v,  MTOT, DD, DD);
    hash_kernel<<<dim3(NN/32, BHN), 256>>>(rot);
    sort_kernel<<<BHN*NHASH, 256>>>();
    attn_kernel<<<(BHN*CHTOT)/4, 128>>>();
    combine_kernel<<<dim3(NN/4, BHN), 256>>>();
    sgemm_k<true><<<ggrid, 256>>>(att, Wout, bout, out, MTOT, DD, DD);
}

// round 2
// speedup vs baseline: 2.5700x; 2.5700x over previous
#include <cuda_runtime.h>
#include <math.h>

// ---------------- problem constants ----------------
#define BN     8      // batch
#define NN     1024   // seq len
#define DD     512    // model dim
#define HH     8      // heads
#define DHD    64     // dim per head
#define NHASH  4      // hash rounds
#define NBUCK  256    // buckets per round (N / BUCKET)
#define BSZ    4      // bucket size
#define BHN    (BN*HH)        // 64
#define MTOT   (BN*NN)        // 8192 rows for GEMMs
#define CHTOT  (NHASH*NBUCK)  // 1024 chunks per bh (flat, cross-round)

// ---------------- scratch (device globals; no runtime alloc) ----------------
__device__ float g_qk    [BN*NN*DD];          // 16 MB
__device__ float g_v     [BN*NN*DD];          // 16 MB
__device__ int   g_bucket[BHN*NHASH*NN];      // 1 MB
__device__ int   g_st    [BHN*NHASH*NN];      // 1 MB
__device__ float g_o     [(size_t)BHN*NHASH*NN*DHD]; // 64 MB
__device__ float g_logits[BHN*NHASH*NN];      // 1 MB
__device__ float g_att   [BN*NN*DD];          // 16 MB

// ---------------- K1/K6: SGEMM 128x128 tile, BK=8, double-buffered ----------
// C[M,N] = A[M,K] @ B[K,N] (+bias). 256 threads, 8x8 microtile (4+4 split).
template<bool HASBIAS>
__global__ __launch_bounds__(256) void sgemm128(
    const float* __restrict__ A, const float* __restrict__ Bm,
    const float* __restrict__ bias, float* __restrict__ C,
    int M, int Nn, int K)
{
    __shared__ float As[2][8][132];
    __shared__ float Bs[2][8][132];
    int tid = threadIdx.x;
    int bm = blockIdx.y * 128, bn = blockIdx.x * 128;
    int ty = tid >> 4, tx = tid & 15;

    int arow = tid >> 1;            // 0..127
    int akq  = (tid & 1) * 4;       // 0 or 4
    int bk   = tid >> 5;            // 0..7
    int bnq  = (tid & 31) * 4;      // 0..124

    const float* Aptr = A  + (size_t)(bm + arow) * K + akq;
    const float* Bptr = Bm + (size_t)bk * Nn + bn + bnq;

    float acc[2][2][4][4];
    #pragma unroll
    for (int a0 = 0; a0 < 2; a0++)
        #pragma unroll
        for (int b0 = 0; b0 < 2; b0++)
            #pragma unroll
            for (int i = 0; i < 4; i++)
                #pragma unroll
                for (int j = 0; j < 4; j++) acc[a0][b0][i][j] = 0.f;

    // prologue: tile 0 -> buffer 0
    float4 av = *(const float4*)(Aptr);
    float4 bv = *(const float4*)(Bptr);
    As[0][akq+0][arow] = av.x;
    As[0][akq+1][arow] = av.y;
    As[0][akq+2][arow] = av.z;
    As[0][akq+3][arow] = av.w;
    *(float4*)&Bs[0][bk][bnq] = bv;
    __syncthreads();

    int buf = 0;
    for (int k0 = 8; k0 < K; k0 += 8) {
        av = *(const float4*)(Aptr + k0);
        bv = *(const float4*)(Bptr + (size_t)k0 * Nn);
        #pragma unroll
        for (int k = 0; k < 8; k++) {
            float4 a0 = *(const float4*)&As[buf][k][ty*4];
            float4 a1 = *(const float4*)&As[buf][k][64 + ty*4];
            float4 b0 = *(const float4*)&Bs[buf][k][tx*4];
            float4 b1 = *(const float4*)&Bs[buf][k][64 + tx*4];
            float aa[2][4] = {{a0.x,a0.y,a0.z,a0.w},{a1.x,a1.y,a1.z,a1.w}};
            float bb[2][4] = {{b0.x,b0.y,b0.z,b0.w},{b1.x,b1.y,b1.z,b1.w}};
            #pragma unroll
            for (int rh = 0; rh < 2; rh++)
                #pragma unroll
                for (int ch = 0; ch < 2; ch++)
                    #pragma unroll
                    for (int i = 0; i < 4; i++)
                        #pragma unroll
                        for (int j = 0; j < 4; j++)
                            acc[rh][ch][i][j] = fmaf(aa[rh][i], bb[ch][j], acc[rh][ch][i][j]);
        }
        buf ^= 1;
        As[buf][akq+0][arow] = av.x;
        As[buf][akq+1][arow] = av.y;
        As[buf][akq+2][arow] = av.z;
        As[buf][akq+3][arow] = av.w;
        *(float4*)&Bs[buf][bk][bnq] = bv;
        __syncthreads();
    }
    // final tile
    #pragma unroll
    for (int k = 0; k < 8; k++) {
        float4 a0 = *(const float4*)&As[buf][k][ty*4];
        float4 a1 = *(const float4*)&As[buf][k][64 + ty*4];
        float4 b0 = *(const float4*)&Bs[buf][k][tx*4];
        float4 b1 = *(const float4*)&Bs[buf][k][64 + tx*4];
        float aa[2][4] = {{a0.x,a0.y,a0.z,a0.w},{a1.x,a1.y,a1.z,a1.w}};
        float bb[2][4] = {{b0.x,b0.y,b0.z,b0.w},{b1.x,b1.y,b1.z,b1.w}};
        #pragma unroll
        for (int rh = 0; rh < 2; rh++)
            #pragma unroll
            for (int ch = 0; ch < 2; ch++)
                #pragma unroll
                for (int i = 0; i < 4; i++)
                    #pragma unroll
                    for (int j = 0; j < 4; j++)
                        acc[rh][ch][i][j] = fmaf(aa[rh][i], bb[ch][j], acc[rh][ch][i][j]);
    }

    #pragma unroll
    for (int rh = 0; rh < 2; rh++)
        #pragma unroll
        for (int i = 0; i < 4; i++) {
            int row = bm + rh*64 + ty*4 + i;
            #pragma unroll
            for (int ch = 0; ch < 2; ch++) {
                float4 o;
                o.x = acc[rh][ch][i][0]; o.y = acc[rh][ch][i][1];
                o.z = acc[rh][ch][i][2]; o.w = acc[rh][ch][i][3];
                int col = bn + ch*64 + tx*4;
                if (HASBIAS) {
                    o.x += bias[col+0]; o.y += bias[col+1];
                    o.z += bias[col+2]; o.w += bias[col+3];
                }
                *(float4*)(C + (size_t)row * Nn + col) = o;
            }
        }
}

// ---------------- K2: LSH hashing, register-blocked 4 tok x 16 i ------------
// Block: 128 threads = 16 token-quads x 8 i-groups. 64 tokens per block.
__global__ __launch_bounds__(128) void hash_kernel(const float* __restrict__ rot)
{
    __shared__ float qs[64][64];    // 16 KB
    __shared__ float rs[64][128];   // 32 KB
    int bh = blockIdx.y;
    int t0 = blockIdx.x * 64;
    int b = bh >> 3, h = bh & 7;
    int tid = threadIdx.x;
    int quad = tid >> 3, ig = tid & 7;

    for (int idx = tid; idx < 64*16; idx += 128) {
        int tk = idx >> 4, fq = (idx & 15) * 4;
        *(float4*)&qs[tk][fq] =
            *(const float4*)(g_qk + ((size_t)(b*NN + t0 + tk))*DD + h*DHD + fq);
    }

    for (int r = 0; r < NHASH; r++) {
        __syncthreads();   // qs ready / previous round done with rs
        for (int idx = tid; idx < 64*32; idx += 128) {
            int f = idx >> 5, iq = (idx & 31) * 4;
            *(float4*)&rs[f][iq] = *(const float4*)(rot + f*(NHASH*128) + r*128 + iq);
        }
        __syncthreads();

        float acc[4][4][4];   // [token tt][c][j], i = ig*4 + c*32 + j
        #pragma unroll
        for (int tt = 0; tt < 4; tt++)
            #pragma unroll
            for (int c = 0; c < 4; c++)
                #pragma unroll
                for (int j = 0; j < 4; j++) acc[tt][c][j] = 0.f;

        for (int f = 0; f < 64; f++) {
            float q[4];
            #pragma unroll
            for (int tt = 0; tt < 4; tt++) q[tt] = qs[quad*4 + tt][f];
            #pragma unroll
            for (int c = 0; c < 4; c++) {
                float4 rv = *(const float4*)&rs[f][ig*4 + c*32];
                float rr[4] = {rv.x, rv.y, rv.z, rv.w};
                #pragma unroll
                for (int tt = 0; tt < 4; tt++)
                    #pragma unroll
                    for (int j = 0; j < 4; j++)
                        acc[tt][c][j] = fmaf(q[tt], rr[j], acc[tt][c][j]);
            }
        }

        // argmax over concat([rot, -rot]) with first-index-wins tie-break
        #pragma unroll
        for (int tt = 0; tt < 4; tt++) {
            float bvv = -1e30f; int bi = 256;
            #pragma unroll
            for (int c = 0; c < 4; c++)
                #pragma unroll
                for (int j = 0; j < 4; j++) {
                    int i = ig*4 + c*32 + j;
                    float v = acc[tt][c][j];
                    if (v > bvv || (v == bvv && i < bi)) { bvv = v; bi = i; }
                    float vn = -v; int i2 = 128 + i;
                    if (vn > bvv || (vn == bvv && i2 < bi)) { bvv = vn; bi = i2; }
                }
            #pragma unroll
            for (int m = 1; m < 8; m <<= 1) {
                float ov = __shfl_xor_sync(0xffffffffu, bvv, m);
                int   oi = __shfl_xor_sync(0xffffffffu, bi, m);
                if (ov > bvv || (ov == bvv && oi < bi)) { bvv = ov; bi = oi; }
            }
            if (ig == 0)
                g_bucket[(bh*NHASH + r)*NN + t0 + quad*4 + tt] = bi;
        }
    }
}

// ---------------- K3: stable counting sort per (bh, round) ------------------
__global__ __launch_bounds__(256) void sort_kernel()
{
    __shared__ int bks[NN];
    __shared__ int hist[NBUCK];
    __shared__ int offs[NBUCK];
    int bhr = blockIdx.x;              // bh*NHASH + r
    int tid = threadIdx.x;
    for (int t = tid; t < NN; t += 256) bks[t] = g_bucket[bhr*NN + t];
    hist[tid] = 0;
    __syncthreads();
    for (int t = tid; t < NN; t += 256) atomicAdd(&hist[bks[t]], 1);
    __syncthreads();
    if (tid == 0) {
        int s = 0;
        for (int bkt = 0; bkt < NBUCK; bkt++) { offs[bkt] = s; s += hist[bkt]; }
    }
    __syncthreads();
    int mybkt = tid;                   // one bucket per thread; stable by position
    int off = offs[mybkt];
    for (int t = 0; t < NN; t++)
        if (bks[t] == mybkt) { g_st[bhr*NN + off] = t; off++; }
}

// ---------------- K4: chunked attention, warp per chunk ---------------------
// look_one_back runs over the FLAT 1024-chunk axis (crosses hash rounds).
__global__ __launch_bounds__(128) void attn_kernel()
{
    __shared__ float qs[4][4][68];
    __shared__ float ks[4][8][68];
    __shared__ float vs[4][8][68];
    __shared__ float ps[4][4][8];
    __shared__ int   tqa[4][4];
    __shared__ int   tka[4][8];
    int w = threadIdx.x >> 5;
    int lane = threadIdx.x & 31;
    int C = blockIdx.x * 4 + w;                 // global (bh, flat chunk)
    int bh = C >> 10;
    int Cl = C & 1023;
    int r = Cl >> 8, c = Cl & 255;
    int Cp = (Cl + 1023) & 1023;                // previous chunk (wraps rounds)
    int rp = Cp >> 8, cp = Cp & 255;
    int b = bh >> 3, h = bh & 7;

    if (lane < 4) {
        int t = g_st[(bh*NHASH + r)*NN + c*BSZ + lane];
        tqa[w][lane] = t;
        tka[w][lane] = t;
        tka[w][lane + 4] = g_st[(bh*NHASH + rp)*NN + cp*BSZ + lane];
    }
    __syncwarp();

    #pragma unroll
    for (int i = 0; i < 4; i++) {
        const float* src = g_qk + ((size_t)(b*NN + tqa[w][i]))*DD + h*DHD;
        qs[w][i][lane]      = src[lane];
        qs[w][i][lane + 32] = src[lane + 32];
    }
    #pragma unroll
    for (int j = 0; j < 8; j++) {
        int t = tka[w][j];
        const float* ksrc = g_qk + ((size_t)(b*NN + t))*DD + h*DHD;
        const float* vsrc = g_v  + ((size_t)(b*NN + t))*DD + h*DHD;
        float k0 = ksrc[lane], k1 = ksrc[lane + 32];
        vs[w][j][lane]      = vsrc[lane];
        vs[w][j][lane + 32] = vsrc[lane + 32];
        float ss = k0*k0 + k1*k1;
        #pragma unroll
        for (int d = 16; d >= 1; d >>= 1) ss += __shfl_xor_sync(0xffffffffu, ss, d);
        float scale = 1.0f / fmaxf(sqrtf(ss), 1e-6f);   // make_unit_length
        ks[w][j][lane]      = k0 * scale;
        ks[w][j][lane + 32] = k1 * scale;
    }
    __syncwarp();

    int i = lane >> 3, j = lane & 7;            // 32 lanes = 4x8 dot products
    float d = 0.f;
    #pragma unroll
    for (int f = 0; f < 64; f++)
        d = fmaf(qs[w][i][f], ks[w][j][f], d);
    d *= 0.125f;                                 // dh^-0.5
    if (tqa[w][i] == tka[w][j]) d = -5e4f;       // self-token mask (by id!)

    float m = d;
    #pragma unroll
    for (int dd = 4; dd >= 1; dd >>= 1) m = fmaxf(m, __shfl_xor_sync(0xffffffffu, m, dd));
    float e = expf(d - m);
    float s = e;
    #pragma unroll
    for (int dd = 4; dd >= 1; dd >>= 1) s += __shfl_xor_sync(0xffffffffu, s, dd);
    float lse = m + logf(s);
    ps[w][i][j] = e / s;
    __syncwarp();

    #pragma unroll
    for (int it = 0; it < 8; it++) {
        int idx = it * 32 + lane;
        int oi = idx >> 6, f = idx & 63;
        float acc = 0.f;
        #pragma unroll
        for (int jj = 0; jj < 8; jj++)
            acc = fmaf(ps[w][oi][jj], vs[w][jj][f], acc);
        // scatter-unsort directly by token id
        g_o[(((size_t)(bh*NHASH + r))*NN + tqa[w][oi])*DHD + f] = acc;
    }
    if (j == 0)
        g_logits[(bh*NHASH + r)*NN + tqa[w][i]] = lse;
}

// ---------------- K5: combine hash rounds + merge heads ---------------------
__global__ __launch_bounds__(256) void combine_kernel()
{
    int bh = blockIdx.y;
    int t = blockIdx.x * 4 + (threadIdx.x >> 6);
    int f = threadIdx.x & 63;
    int b = bh >> 3, h = bh & 7;
    float l[NHASH];
    #pragma unroll
    for (int r = 0; r < NHASH; r++) l[r] = g_logits[(bh*NHASH + r)*NN + t];
    float m = fmaxf(fmaxf(l[0], l[1]), fmaxf(l[2], l[3]));
    float s = 0.f;
    #pragma unroll
    for (int r = 0; r < NHASH; r++) s += expf(l[r] - m);
    float acc = 0.f;
    #pragma unroll
    for (int r = 0; r < NHASH; r++) {
        float wr = expf(l[r] - m) / s;
        acc = fmaf(wr, g_o[(((size_t)(bh*NHASH + r))*NN + t)*DHD + f], acc);
    }
    g_att[((size_t)(b*NN + t))*DD + h*DHD + f] = acc;
}

// ---------------- launch ----------------------------------------------------
extern "C" void kernel_launch(void* const* d_in, const int* in_sizes, int n_in,
                              void* d_out, int out_size)
{
    (void)in_sizes; (void)n_in; (void)out_size;
    const float* queries = (const float*)d_in[0];
    // d_in[1] keys, d_in[2] values, d_in[8] attn_mask: unused by ReformerLayer
    const float* Wqk  = (const float*)d_in[3];
    const float* Wv   = (const float*)d_in[4];
    const float* Wout = (const float*)d_in[5];
    const float* bout = (const float*)d_in[6];
    const float* rot  = (const float*)d_in[7];
    float* out = (float*)d_out;

    float *qk, *v, *att;
    cudaGetSymbolAddress((void**)&qk,  g_qk);
    cudaGetSymbolAddress((void**)&v,   g_v);
    cudaGetSymbolAddress((void**)&att, g_att);

    dim3 ggrid(DD/128, MTOT/128);   // (4, 64) = 256 blocks
    sgemm128<false><<<ggrid, 256>>>(queries, Wqk, nullptr, qk, MTOT, DD, DD);
    sgemm128<false><<<ggrid, 256>>>(queries, Wv,  nullptr, v,  MTOT, DD, DD);
    hash_kernel<<<dim3(NN/64, BHN), 128>>>(rot);
    sort_kernel<<<BHN*NHASH, 256>>>();
    attn_kernel<<<(BHN*CHTOT)/4, 128>>>();
    combine_kernel<<<dim3(NN/4, BHN), 256>>>();
    sgemm128<true><<<ggrid, 256>>>(att, Wout, bout, out, MTOT, DD, DD);
}

// round 4
// speedup vs baseline: 2.6057x; 1.0139x over previous
#include <cuda_runtime.h>
#include <math.h>

// ---------------- problem constants ----------------
#define BN     8      // batch
#define NN     1024   // seq len
#define DD     512    // model dim
#define HH     8      // heads
#define DHD    64     // dim per head
#define NHASH  4      // hash rounds
#define NBUCK  256    // buckets per round (N / BUCKET)
#define BSZ    4      // bucket size
#define BHN    (BN*HH)        // 64
#define MTOT   (BN*NN)        // 8192 rows for GEMMs
#define CHTOT  (NHASH*NBUCK)  // 1024 chunks per bh (flat, cross-round)

// ---------------- scratch (device globals; no runtime alloc) ----------------
__device__ float g_qk    [BN*NN*DD];          // 16 MB
__device__ float g_v     [BN*NN*DD];          // 16 MB
__device__ int   g_bucket[BHN*NHASH*NN];      // 1 MB
__device__ int   g_st    [BHN*NHASH*NN];      // 1 MB
__device__ float g_o     [(size_t)BHN*NHASH*NN*DHD]; // 64 MB
__device__ float g_logits[BHN*NHASH*NN];      // 1 MB
__device__ float g_att   [BN*NN*DD];          // 16 MB

// ---------------- K1/K6: SGEMM 128x128 tile, BK=8, double-buffered ----------
template<bool HASBIAS>
__global__ __launch_bounds__(256) void sgemm128(
    const float* __restrict__ A, const float* __restrict__ Bm,
    const float* __restrict__ bias, float* __restrict__ C,
    int M, int Nn, int K)
{
    __shared__ float As[2][8][132];
    __shared__ float Bs[2][8][132];
    int tid = threadIdx.x;
    int bm = blockIdx.y * 128, bn = blockIdx.x * 128;
    int ty = tid >> 4, tx = tid & 15;

    int arow = tid >> 1;            // 0..127
    int akq  = (tid & 1) * 4;       // 0 or 4
    int bk   = tid >> 5;            // 0..7
    int bnq  = (tid & 31) * 4;      // 0..124

    const float* Aptr = A  + (size_t)(bm + arow) * K + akq;
    const float* Bptr = Bm + (size_t)bk * Nn + bn + bnq;

    float acc[2][2][4][4];
    #pragma unroll
    for (int a0 = 0; a0 < 2; a0++)
        #pragma unroll
        for (int b0 = 0; b0 < 2; b0++)
            #pragma unroll
            for (int i = 0; i < 4; i++)
                #pragma unroll
                for (int j = 0; j < 4; j++) acc[a0][b0][i][j] = 0.f;

    float4 av = *(const float4*)(Aptr);
    float4 bv = *(const float4*)(Bptr);
    As[0][akq+0][arow] = av.x;
    As[0][akq+1][arow] = av.y;
    As[0][akq+2][arow] = av.z;
    As[0][akq+3][arow] = av.w;
    *(float4*)&Bs[0][bk][bnq] = bv;
    __syncthreads();

    int buf = 0;
    for (int k0 = 8; k0 < K; k0 += 8) {
        av = *(const float4*)(Aptr + k0);
        bv = *(const float4*)(Bptr + (size_t)k0 * Nn);
        #pragma unroll
        for (int k = 0; k < 8; k++) {
            float4 a0 = *(const float4*)&As[buf][k][ty*4];
            float4 a1 = *(const float4*)&As[buf][k][64 + ty*4];
            float4 b0 = *(const float4*)&Bs[buf][k][tx*4];
            float4 b1 = *(const float4*)&Bs[buf][k][64 + tx*4];
            float aa[2][4] = {{a0.x,a0.y,a0.z,a0.w},{a1.x,a1.y,a1.z,a1.w}};
            float bb[2][4] = {{b0.x,b0.y,b0.z,b0.w},{b1.x,b1.y,b1.z,b1.w}};
            #pragma unroll
            for (int rh = 0; rh < 2; rh++)
                #pragma unroll
                for (int ch = 0; ch < 2; ch++)
                    #pragma unroll
                    for (int i = 0; i < 4; i++)
                        #pragma unroll
                        for (int j = 0; j < 4; j++)
                            acc[rh][ch][i][j] = fmaf(aa[rh][i], bb[ch][j], acc[rh][ch][i][j]);
        }
        buf ^= 1;
        As[buf][akq+0][arow] = av.x;
        As[buf][akq+1][arow] = av.y;
        As[buf][akq+2][arow] = av.z;
        As[buf][akq+3][arow] = av.w;
        *(float4*)&Bs[buf][bk][bnq] = bv;
        __syncthreads();
    }
    #pragma unroll
    for (int k = 0; k < 8; k++) {
        float4 a0 = *(const float4*)&As[buf][k][ty*4];
        float4 a1 = *(const float4*)&As[buf][k][64 + ty*4];
        float4 b0 = *(const float4*)&Bs[buf][k][tx*4];
        float4 b1 = *(const float4*)&Bs[buf][k][64 + tx*4];
        float aa[2][4] = {{a0.x,a0.y,a0.z,a0.w},{a1.x,a1.y,a1.z,a1.w}};
        float bb[2][4] = {{b0.x,b0.y,b0.z,b0.w},{b1.x,b1.y,b1.z,b1.w}};
        #pragma unroll
        for (int rh = 0; rh < 2; rh++)
            #pragma unroll
            for (int ch = 0; ch < 2; ch++)
                #pragma unroll
                for (int i = 0; i < 4; i++)
                    #pragma unroll
                    for (int j = 0; j < 4; j++)
                        acc[rh][ch][i][j] = fmaf(aa[rh][i], bb[ch][j], acc[rh][ch][i][j]);
    }

    #pragma unroll
    for (int rh = 0; rh < 2; rh++)
        #pragma unroll
        for (int i = 0; i < 4; i++) {
            int row = bm + rh*64 + ty*4 + i;
            #pragma unroll
            for (int ch = 0; ch < 2; ch++) {
                float4 o;
                o.x = acc[rh][ch][i][0]; o.y = acc[rh][ch][i][1];
                o.z = acc[rh][ch][i][2]; o.w = acc[rh][ch][i][3];
                int col = bn + ch*64 + tx*4;
                if (HASBIAS) {
                    o.x += bias[col+0]; o.y += bias[col+1];
                    o.z += bias[col+2]; o.w += bias[col+3];
                }
                *(float4*)(C + (size_t)row * Nn + col) = o;
            }
        }
}

// ---------------- K2: LSH hashing, register-blocked 4 tok x 16 i ------------
__global__ __launch_bounds__(128) void hash_kernel(const float* __restrict__ rot)
{
    __shared__ float qs[64][64];    // 16 KB
    __shared__ float rs[64][128];   // 32 KB
    int bh = blockIdx.y;
    int t0 = blockIdx.x * 64;
    int b = bh >> 3, h = bh & 7;
    int tid = threadIdx.x;
    int quad = tid >> 3, ig = tid & 7;

    for (int idx = tid; idx < 64*16; idx += 128) {
        int tk = idx >> 4, fq = (idx & 15) * 4;
        *(float4*)&qs[tk][fq] =
            *(const float4*)(g_qk + ((size_t)(b*NN + t0 + tk))*DD + h*DHD + fq);
    }

    for (int r = 0; r < NHASH; r++) {
        __syncthreads();   // qs ready / previous round done with rs
        for (int idx = tid; idx < 64*32; idx += 128) {
            int f = idx >> 5, iq = (idx & 31) * 4;
            *(float4*)&rs[f][iq] = *(const float4*)(rot + f*(NHASH*128) + r*128 + iq);
        }
        __syncthreads();

        float acc[4][4][4];   // [token tt][c][j], i = ig*4 + c*32 + j
        #pragma unroll
        for (int tt = 0; tt < 4; tt++)
            #pragma unroll
            for (int c = 0; c < 4; c++)
                #pragma unroll
                for (int j = 0; j < 4; j++) acc[tt][c][j] = 0.f;

        for (int f = 0; f < 64; f++) {
            float q[4];
            #pragma unroll
            for (int tt = 0; tt < 4; tt++) q[tt] = qs[quad*4 + tt][f];
            #pragma unroll
            for (int c = 0; c < 4; c++) {
                float4 rv = *(const float4*)&rs[f][ig*4 + c*32];
                float rr[4] = {rv.x, rv.y, rv.z, rv.w};
                #pragma unroll
                for (int tt = 0; tt < 4; tt++)
                    #pragma unroll
                    for (int j = 0; j < 4; j++)
                        acc[tt][c][j] = fmaf(q[tt], rr[j], acc[tt][c][j]);
            }
        }

        #pragma unroll
        for (int tt = 0; tt < 4; tt++) {
            float bvv = -1e30f; int bi = 256;
            #pragma unroll
            for (int c = 0; c < 4; c++)
                #pragma unroll
                for (int j = 0; j < 4; j++) {
                    int i = ig*4 + c*32 + j;
                    float v = acc[tt][c][j];
                    if (v > bvv || (v == bvv && i < bi)) { bvv = v; bi = i; }
                    float vn = -v; int i2 = 128 + i;
                    if (vn > bvv || (vn == bvv && i2 < bi)) { bvv = vn; bi = i2; }
                }
            #pragma unroll
            for (int m = 1; m < 8; m <<= 1) {
                float ov = __shfl_xor_sync(0xffffffffu, bvv, m);
                int   oi = __shfl_xor_sync(0xffffffffu, bi, m);
                if (ov > bvv || (ov == bvv && oi < bi)) { bvv = ov; bi = oi; }
            }
            if (ig == 0)
                g_bucket[(bh*NHASH + r)*NN + t0 + quad*4 + tt] = bi;
        }
    }
}

// ---------------- K3: stable counting sort per (bh, round) ------------------
__global__ __launch_bounds__(256) void sort_kernel()
{
    __shared__ __align__(16) int bks[NN];
    __shared__ int hist[NBUCK];
    __shared__ int offs[NBUCK];
    __shared__ int wsum[8];
    int bhr = blockIdx.x;              // bh*NHASH + r
    int tid = threadIdx.x;
    for (int t = tid; t < NN; t += 256) bks[t] = g_bucket[bhr*NN + t];
    hist[tid] = 0;
    __syncthreads();
    for (int t = tid; t < NN; t += 256) atomicAdd(&hist[bks[t]], 1);
    __syncthreads();
    // parallel exclusive scan of hist (warp shuffle + 8-way carry)
    int hv = hist[tid];
    int incl = hv;
    #pragma unroll
    for (int d = 1; d < 32; d <<= 1) {
        int nv = __shfl_up_sync(0xffffffffu, incl, d);
        if ((tid & 31) >= d) incl += nv;
    }
    if ((tid & 31) == 31) wsum[tid >> 5] = incl;
    __syncthreads();
    if (tid == 0) {
        int s = 0;
        #pragma unroll
        for (int k = 0; k < 8; k++) { int t = wsum[k]; wsum[k] = s; s += t; }
    }
    __syncthreads();
    offs[tid] = incl - hv + wsum[tid >> 5];
    __syncthreads();
    // each thread owns one bucket; scan tokens via int4 smem broadcast
    int mybkt = tid;                   // stable by position
    int off = offs[mybkt];
    const int4* b4 = (const int4*)bks;
    for (int t4 = 0; t4 < NN/4; t4++) {
        int4 v = b4[t4];
        if (v.x == mybkt) g_st[bhr*NN + off++] = t4*4 + 0;
        if (v.y == mybkt) g_st[bhr*NN + off++] = t4*4 + 1;
        if (v.z == mybkt) g_st[bhr*NN + off++] = t4*4 + 2;
        if (v.w == mybkt) g_st[bhr*NN + off++] = t4*4 + 3;
    }
}

// ---------------- K4: chunked attention, warp per chunk ---------------------
// look_one_back runs over the FLAT 1024-chunk axis (crosses hash rounds).
__global__ __launch_bounds__(128) void attn_kernel()
{
    __shared__ __align__(16) float qs[4][4][68];
    __shared__ __align__(16) float ks[4][8][68];
    __shared__ __align__(16) float vs[4][8][68];
    __shared__ float ps[4][4][8];
    __shared__ int   tka[4][8];
    int w = threadIdx.x >> 5;
    int lane = threadIdx.x & 31;
    int C = blockIdx.x * 4 + w;                 // global (bh, flat chunk)
    int bh = C >> 10;
    int Cl = C & 1023;
    int r = Cl >> 8, c = Cl & 255;
    int Cp = (Cl + 1023) & 1023;                // previous chunk (wraps rounds)
    int rp = Cp >> 8, cp = Cp & 255;
    int b = bh >> 3, h = bh & 7;

    if (lane < 4) {
        tka[w][lane]     = g_st[(bh*NHASH + r)*NN + c*BSZ + lane];
        tka[w][lane + 4] = g_st[(bh*NHASH + rp)*NN + cp*BSZ + lane];
    }
    __syncwarp();

    // 8 qk rows + 8 v rows; q-rows (j<4) written raw AND normalized (k role)
    #pragma unroll
    for (int j = 0; j < 8; j++) {
        int t = tka[w][j];
        const float* ksrc = g_qk + ((size_t)(b*NN + t))*DD + h*DHD;
        const float* vsrc = g_v  + ((size_t)(b*NN + t))*DD + h*DHD;
        float k0 = ksrc[lane], k1 = ksrc[lane + 32];
        vs[w][j][lane]      = vsrc[lane];
        vs[w][j][lane + 32] = vsrc[lane + 32];
        if (j < 4) { qs[w][j][lane] = k0; qs[w][j][lane + 32] = k1; }
        float ss = k0*k0 + k1*k1;
        #pragma unroll
        for (int d = 16; d >= 1; d >>= 1) ss += __shfl_xor_sync(0xffffffffu, ss, d);
        float scale = 1.0f / fmaxf(sqrtf(ss), 1e-6f);   // make_unit_length
        ks[w][j][lane]      = k0 * scale;
        ks[w][j][lane + 32] = k1 * scale;
    }
    __syncwarp();

    int i = lane >> 3, j = lane & 7;            // 32 lanes = 4x8 dot products
    const float4* q4 = (const float4*)qs[w][i];
    const float4* k4 = (const float4*)ks[w][j];
    float d = 0.f;
    #pragma unroll
    for (int fq = 0; fq < 16; fq++) {
        float4 a = q4[fq], kk = k4[fq];
        d = fmaf(a.x, kk.x, d);
        d = fmaf(a.y, kk.y, d);
        d = fmaf(a.z, kk.z, d);
        d = fmaf(a.w, kk.w, d);
    }
    d *= 0.125f;                                 // dh^-0.5
    if (tka[w][i] == tka[w][j]) d = -5e4f;       // self-token mask (by id!)

    float m = d;
    #pragma unroll
    for (int dd = 4; dd >= 1; dd >>= 1) m = fmaxf(m, __shfl_xor_sync(0xffffffffu, m, dd));
    float e = expf(d - m);
    float s = e;
    #pragma unroll
    for (int dd = 4; dd >= 1; dd >>= 1) s += __shfl_xor_sync(0xffffffffu, s, dd);
    float lse = m + logf(s);
    ps[w][i][j] = e / s;
    __syncwarp();

    #pragma unroll
    for (int it = 0; it < 8; it++) {
        int idx = it * 32 + lane;
        int oi = idx >> 6, f = idx & 63;
        float acc = 0.f;
        #pragma unroll
        for (int jj = 0; jj < 8; jj++)
            acc = fmaf(ps[w][oi][jj], vs[w][jj][f], acc);
        // scatter-unsort directly by token id
        g_o[(((size_t)(bh*NHASH + r))*NN + tka[w][oi])*DHD + f] = acc;
    }
    if (j == 0)
        g_logits[(bh*NHASH + r)*NN + tka[w][i]] = lse;
}

// ---------------- K5: combine hash rounds + merge heads ---------------------
__global__ __launch_bounds__(256) void combine_kernel()
{
    int bh = blockIdx.y;
    int t = blockIdx.x * 4 + (threadIdx.x >> 6);
    int f = threadIdx.x & 63;
    int b = bh >> 3, h = bh & 7;
    float l[NHASH];
    #pragma unroll
    for (int r = 0; r < NHASH; r++) l[r] = g_logits[(bh*NHASH + r)*NN + t];
    float m = fmaxf(fmaxf(l[0], l[1]), fmaxf(l[2], l[3]));
    float s = 0.f;
    #pragma unroll
    for (int r = 0; r < NHASH; r++) s += expf(l[r] - m);
    float acc = 0.f;
    #pragma unroll
    for (int r = 0; r < NHASH; r++) {
        float wr = expf(l[r] - m) / s;
        acc = fmaf(wr, g_o[(((size_t)(bh*NHASH + r))*NN + t)*DHD + f], acc);
    }
    g_att[((size_t)(b*NN + t))*DD + h*DHD + f] = acc;
}

// ---------------- launch ----------------------------------------------------
extern "C" void kernel_launch(void* const* d_in, const int* in_sizes, int n_in,
                              void* d_out, int out_size)
{
    (void)in_sizes; (void)n_in; (void)out_size;
    const float* queries = (const float*)d_in[0];
    // d_in[1] keys, d_in[2] values, d_in[8] attn_mask: unused by ReformerLayer
    const float* Wqk  = (const float*)d_in[3];
    const float* Wv   = (const float*)d_in[4];
    const float* Wout = (const float*)d_in[5];
    const float* bout = (const float*)d_in[6];
    const float* rot  = (const float*)d_in[7];
    float* out = (float*)d_out;

    float *qk, *v, *att;
    cudaGetSymbolAddress((void**)&qk,  g_qk);
    cudaGetSymbolAddress((void**)&v,   g_v);
    cudaGetSymbolAddress((void**)&att, g_att);

    dim3 ggrid(DD/128, MTOT/128);   // (4, 64) = 256 blocks
    sgemm128<false><<<ggrid, 256>>>(queries, Wqk, nullptr, qk, MTOT, DD, DD);
    sgemm128<false><<<ggrid, 256>>>(queries, Wv,  nullptr, v,  MTOT, DD, DD);
    hash_kernel<<<dim3(NN/64, BHN), 128>>>(rot);
    sort_kernel<<<BHN*NHASH, 256>>>();
    attn_kernel<<<(BHN*CHTOT)/4, 128>>>();
    combine_kernel<<<dim3(NN/4, BHN), 256>>>();
    sgemm128<true><<<ggrid, 256>>>(att, Wout, bout, out, MTOT, DD, DD);
}

// round 6
// speedup vs baseline: 2.7517x; 1.0560x over previous
#include <cuda_runtime.h>
#include <math.h>

// ---------------- problem constants ----------------
#define BN     8      // batch
#define NN     1024   // seq len
#define DD     512    // model dim
#define HH     8      // heads
#define DHD    64     // dim per head
#define NHASH  4      // hash rounds
#define NBUCK  256    // buckets per round (N / BUCKET)
#define BSZ    4      // bucket size
#define BHN    (BN*HH)        // 64
#define MTOT   (BN*NN)        // 8192 rows for GEMMs
#define CHTOT  (NHASH*NBUCK)  // 1024 chunks per bh (flat, cross-round)

typedef unsigned long long ull;

// ---- packed f32x2 helpers (FFMA2 path; bit-exact fp32, 2 lanes/instr) ------
__device__ __forceinline__ ull pack2(float lo, float hi) {
    ull r; asm("mov.b64 %0, {%1, %2};" : "=l"(r) : "f"(lo), "f"(hi)); return r;
}
__device__ __forceinline__ void unpack2(ull v, float& lo, float& hi) {
    asm("mov.b64 {%0, %1}, %2;" : "=f"(lo), "=f"(hi) : "l"(v));
}
__device__ __forceinline__ void fma2(ull& d, ull a, ull b) {
    asm("fma.rn.f32x2 %0, %1, %2, %0;" : "+l"(d) : "l"(a), "l"(b));
}

// ---------------- scratch (device globals; no runtime alloc) ----------------
__device__ float g_qk    [BN*NN*DD];          // 16 MB
__device__ float g_v     [BN*NN*DD];          // 16 MB
__device__ int   g_bucket[BHN*NHASH*NN];      // 1 MB
__device__ int   g_st    [BHN*NHASH*NN];      // 1 MB
__device__ float g_o     [(size_t)BHN*NHASH*NN*DHD]; // 64 MB
__device__ float g_logits[BHN*NHASH*NN];      // 1 MB
__device__ float g_att   [BN*NN*DD];          // 16 MB

// ---------------- K1/K6: SGEMM 128x128 tile, BK=8, double-buffered, FFMA2 ---
// acc[i][jp]: i = 8 rows (4 + 4 split), jp = 4 col-pairs (2 + 2 split).
template<bool HASBIAS>
__global__ __launch_bounds__(256, 2) void sgemm128(
    const float* __restrict__ A, const float* __restrict__ Bm,
    const float* __restrict__ bias, float* __restrict__ C,
    int M, int Nn, int K)
{
    __shared__ __align__(16) float As[2][8][132];
    __shared__ __align__(16) float Bs[2][8][132];
    int tid = threadIdx.x;
    int bm = blockIdx.y * 128, bn = blockIdx.x * 128;
    int ty = tid >> 4, tx = tid & 15;

    int arow = tid >> 1;            // 0..127
    int akq  = (tid & 1) * 4;       // 0 or 4
    int bk   = tid >> 5;            // 0..7
    int bnq  = (tid & 31) * 4;      // 0..124

    const float* Aptr = A  + (size_t)(bm + arow) * K + akq;
    const float* Bptr = Bm + (size_t)bk * Nn + bn + bnq;

    ull acc[8][4];
    #pragma unroll
    for (int i = 0; i < 8; i++)
        #pragma unroll
        for (int jp = 0; jp < 4; jp++) acc[i][jp] = 0ull;

    float4 av = *(const float4*)(Aptr);
    float4 bv = *(const float4*)(Bptr);
    As[0][akq+0][arow] = av.x;
    As[0][akq+1][arow] = av.y;
    As[0][akq+2][arow] = av.z;
    As[0][akq+3][arow] = av.w;
    *(float4*)&Bs[0][bk][bnq] = bv;
    __syncthreads();

    int buf = 0;
    for (int k0 = 8; k0 <= K; k0 += 8) {
        if (k0 < K) {
            av = *(const float4*)(Aptr + k0);
            bv = *(const float4*)(Bptr + (size_t)k0 * Nn);
        }
        #pragma unroll
        for (int k = 0; k < 8; k++) {
            float4 a0 = *(const float4*)&As[buf][k][ty*4];
            float4 a1 = *(const float4*)&As[buf][k][64 + ty*4];
            ulonglong2 b0 = *(const ulonglong2*)&Bs[buf][k][tx*4];
            ulonglong2 b1 = *(const ulonglong2*)&Bs[buf][k][64 + tx*4];
            ull ad[8];
            ad[0] = pack2(a0.x, a0.x); ad[1] = pack2(a0.y, a0.y);
            ad[2] = pack2(a0.z, a0.z); ad[3] = pack2(a0.w, a0.w);
            ad[4] = pack2(a1.x, a1.x); ad[5] = pack2(a1.y, a1.y);
            ad[6] = pack2(a1.z, a1.z); ad[7] = pack2(a1.w, a1.w);
            #pragma unroll
            for (int i = 0; i < 8; i++) {
                fma2(acc[i][0], ad[i], b0.x);
                fma2(acc[i][1], ad[i], b0.y);
                fma2(acc[i][2], ad[i], b1.x);
                fma2(acc[i][3], ad[i], b1.y);
            }
        }
        if (k0 < K) {
            buf ^= 1;
            As[buf][akq+0][arow] = av.x;
            As[buf][akq+1][arow] = av.y;
            As[buf][akq+2][arow] = av.z;
            As[buf][akq+3][arow] = av.w;
            *(float4*)&Bs[buf][bk][bnq] = bv;
            __syncthreads();
        }
    }

    #pragma unroll
    for (int rh = 0; rh < 2; rh++)
        #pragma unroll
        for (int i = 0; i < 4; i++) {
            int row = bm + rh*64 + ty*4 + i;
            #pragma unroll
            for (int ch = 0; ch < 2; ch++) {
                float4 o;
                unpack2(acc[rh*4+i][ch*2+0], o.x, o.y);
                unpack2(acc[rh*4+i][ch*2+1], o.z, o.w);
                int col = bn + ch*64 + tx*4;
                if (HASBIAS) {
                    o.x += bias[col+0]; o.y += bias[col+1];
                    o.z += bias[col+2]; o.w += bias[col+3];
                }
                *(float4*)(C + (size_t)row * Nn + col) = o;
            }
        }
}

// ---------------- K2: LSH hashing, FFMA2, 4 tok x 16 i per thread -----------
// Per-j accumulation chains identical to scalar version -> buckets bitwise same.
__global__ __launch_bounds__(128) void hash_kernel(const float* __restrict__ rot)
{
    __shared__ __align__(16) float qs[64][64];    // 16 KB
    __shared__ __align__(16) float rs[64][128];   // 32 KB
    int bh = blockIdx.y;
    int t0 = blockIdx.x * 64;
    int b = bh >> 3, h = bh & 7;
    int tid = threadIdx.x;
    int quad = tid >> 3, ig = tid & 7;

    for (int idx = tid; idx < 64*16; idx += 128) {
        int tk = idx >> 4, fq = (idx & 15) * 4;
        *(float4*)&qs[tk][fq] =
            *(const float4*)(g_qk + ((size_t)(b*NN + t0 + tk))*DD + h*DHD + fq);
    }

    for (int r = 0; r < NHASH; r++) {
        __syncthreads();   // qs ready / previous round done with rs
        for (int idx = tid; idx < 64*32; idx += 128) {
            int f = idx >> 5, iq = (idx & 31) * 4;
            *(float4*)&rs[f][iq] = *(const float4*)(rot + f*(NHASH*128) + r*128 + iq);
        }
        __syncthreads();

        ull acc2[4][4][2];   // [token tt][c][jpair], i = ig*4 + c*32 + jp*2+{0,1}
        #pragma unroll
        for (int tt = 0; tt < 4; tt++)
            #pragma unroll
            for (int c = 0; c < 4; c++) {
                acc2[tt][c][0] = 0ull; acc2[tt][c][1] = 0ull;
            }

        for (int f = 0; f < 64; f++) {
            ull qd[4];
            #pragma unroll
            for (int tt = 0; tt < 4; tt++) {
                float q = qs[quad*4 + tt][f];
                qd[tt] = pack2(q, q);
            }
            #pragma unroll
            for (int c = 0; c < 4; c++) {
                ulonglong2 rv = *(const ulonglong2*)&rs[f][ig*4 + c*32];
                #pragma unroll
                for (int tt = 0; tt < 4; tt++) {
                    fma2(acc2[tt][c][0], qd[tt], rv.x);
                    fma2(acc2[tt][c][1], qd[tt], rv.y);
                }
            }
        }

        #pragma unroll
        for (int tt = 0; tt < 4; tt++) {
            float bvv = -1e30f; int bi = 256;
            #pragma unroll
            for (int c = 0; c < 4; c++)
                #pragma unroll
                for (int jp = 0; jp < 2; jp++) {
                    float v0, v1;
                    unpack2(acc2[tt][c][jp], v0, v1);
                    float vv[2] = {v0, v1};
                    #pragma unroll
                    for (int u = 0; u < 2; u++) {
                        int i = ig*4 + c*32 + jp*2 + u;
                        float v = vv[u];
                        if (v > bvv || (v == bvv && i < bi)) { bvv = v; bi = i; }
                        float vn = -v; int i2 = 128 + i;
                        if (vn > bvv || (vn == bvv && i2 < bi)) { bvv = vn; bi = i2; }
                    }
                }
            #pragma unroll
            for (int m = 1; m < 8; m <<= 1) {
                float ov = __shfl_xor_sync(0xffffffffu, bvv, m);
                int   oi = __shfl_xor_sync(0xffffffffu, bi, m);
                if (ov > bvv || (ov == bvv && oi < bi)) { bvv = ov; bi = oi; }
            }
            if (ig == 0)
                g_bucket[(bh*NHASH + r)*NN + t0 + quad*4 + tt] = bi;
        }
    }
}

// ---------------- K3: stable counting sort per (bh, round) ------------------
// atomic place (unstable) + per-bucket insertion sort by token id = stable.
__global__ __launch_bounds__(256) void sort_kernel()
{
    __shared__ __align__(16) int bks[NN];
    __shared__ int tmp[NN];
    __shared__ int hist[NBUCK];
    __shared__ int offs[NBUCK];
    __shared__ int cnt[NBUCK];
    __shared__ int wsum[8];
    int bhr = blockIdx.x;              // bh*NHASH + r
    int tid = threadIdx.x;
    for (int t = tid; t < NN; t += 256) bks[t] = g_bucket[bhr*NN + t];
    hist[tid] = 0; cnt[tid] = 0;
    __syncthreads();
    for (int t = tid; t < NN; t += 256) atomicAdd(&hist[bks[t]], 1);
    __syncthreads();
    // parallel exclusive scan of hist (warp shuffle + 8-way carry)
    int hv = hist[tid];
    int incl = hv;
    #pragma unroll
    for (int d = 1; d < 32; d <<= 1) {
        int nv = __shfl_up_sync(0xffffffffu, incl, d);
        if ((tid & 31) >= d) incl += nv;
    }
    if ((tid & 31) == 31) wsum[tid >> 5] = incl;
    __syncthreads();
    if (tid == 0) {
        int s = 0;
        #pragma unroll
        for (int k = 0; k < 8; k++) { int t = wsum[k]; wsum[k] = s; s += t; }
    }
    __syncthreads();
    offs[tid] = incl - hv + wsum[tid >> 5];
    __syncthreads();
    // place (order arbitrary within bucket)
    for (int t = tid; t < NN; t += 256) {
        int b = bks[t];
        int p = atomicAdd(&cnt[b], 1);
        tmp[offs[b] + p] = t;
    }
    __syncthreads();
    // stabilize: sort each bucket's segment ascending by token id
    {
        int o = offs[tid], k = hist[tid];
        for (int x = 1; x < k; x++) {
            int key = tmp[o + x];
            int y = x - 1;
            while (y >= 0 && tmp[o + y] > key) { tmp[o + y + 1] = tmp[o + y]; y--; }
            tmp[o + y + 1] = key;
        }
    }
    __syncthreads();
    for (int t = tid; t < NN; t += 256) g_st[bhr*NN + t] = tmp[t];
}

// ---------------- K4: chunked attention, warp per chunk, FFMA2 --------------
// look_one_back runs over the FLAT 1024-chunk axis (crosses hash rounds).
__global__ __launch_bounds__(128) void attn_kernel()
{
    __shared__ __align__(16) float qs[4][4][68];
    __shared__ __align__(16) float ks[4][8][68];
    __shared__ __align__(16) float vs[4][8][68];
    __shared__ float ps[4][4][8];
    __shared__ int   tka[4][8];
    int w = threadIdx.x >> 5;
    int lane = threadIdx.x & 31;
    int C = blockIdx.x * 4 + w;                 // global (bh, flat chunk)
    int bh = C >> 10;
    int Cl = C & 1023;
    int r = Cl >> 8, c = Cl & 255;
    int Cp = (Cl + 1023) & 1023;                // previous chunk (wraps rounds)
    int rp = Cp >> 8, cp = Cp & 255;
    int b = bh >> 3, h = bh & 7;

    if (lane < 4) {
        tka[w][lane]     = g_st[(bh*NHASH + r)*NN + c*BSZ + lane];
        tka[w][lane + 4] = g_st[(bh*NHASH + rp)*NN + cp*BSZ + lane];
    }
    __syncwarp();

    // 8 qk rows + 8 v rows; q-rows (j<4) written raw AND normalized (k role)
    #pragma unroll
    for (int j = 0; j < 8; j++) {
        int t = tka[w][j];
        const float* ksrc = g_qk + ((size_t)(b*NN + t))*DD + h*DHD;
        const float* vsrc = g_v  + ((size_t)(b*NN + t))*DD + h*DHD;
        float k0 = ksrc[lane], k1 = ksrc[lane + 32];
        vs[w][j][lane]      = vsrc[lane];
        vs[w][j][lane + 32] = vsrc[lane + 32];
        if (j < 4) { qs[w][j][lane] = k0; qs[w][j][lane + 32] = k1; }
        float ss = k0*k0 + k1*k1;
        #pragma unroll
        for (int d = 16; d >= 1; d >>= 1) ss += __shfl_xor_sync(0xffffffffu, ss, d);
        float scale = 1.0f / fmaxf(sqrtf(ss), 1e-6f);   // make_unit_length
        ks[w][j][lane]      = k0 * scale;
        ks[w][j][lane + 32] = k1 * scale;
    }
    __syncwarp();

    int i = lane >> 3, j = lane & 7;            // 32 lanes = 4x8 dot products
    const ulonglong2* q2 = (const ulonglong2*)qs[w][i];
    const ulonglong2* k2 = (const ulonglong2*)ks[w][j];
    ull d2 = 0ull;
    #pragma unroll
    for (int fq = 0; fq < 16; fq++) {
        ulonglong2 a = q2[fq], kk = k2[fq];
        fma2(d2, a.x, kk.x);
        fma2(d2, a.y, kk.y);
    }
    float dlo, dhi;
    unpack2(d2, dlo, dhi);
    float d = (dlo + dhi) * 0.125f;              // dh^-0.5
    if (tka[w][i] == tka[w][j]) d = -5e4f;       // self-token mask (by id!)

    float m = d;
    #pragma unroll
    for (int dd = 4; dd >= 1; dd >>= 1) m = fmaxf(m, __shfl_xor_sync(0xffffffffu, m, dd));
    float e = expf(d - m);
    float s = e;
    #pragma unroll
    for (int dd = 4; dd >= 1; dd >>= 1) s += __shfl_xor_sync(0xffffffffu, s, dd);
    float lse = m + logf(s);
    ps[w][i][j] = e / s;
    __syncwarp();

    // output: 4 rows x 32 f-pairs; per it all lanes share oi = it
    #pragma unroll
    for (int it = 0; it < 4; it++) {
        int oi = it, fp = lane;
        ull acc = 0ull;
        #pragma unroll
        for (int jj = 0; jj < 8; jj++) {
            float p = ps[w][oi][jj];
            ull pd = pack2(p, p);
            ull vv = *(const ull*)&vs[w][jj][fp*2];
            fma2(acc, pd, vv);
        }
        *(ull*)&g_o[(((size_t)(bh*NHASH + r))*NN + tka[w][oi])*DHD + fp*2] = acc;
    }
    if (j == 0)
        g_logits[(bh*NHASH + r)*NN + tka[w][i]] = lse;
}

// ---------------- K5: combine hash rounds + merge heads (FFMA2) -------------
__global__ __launch_bounds__(256) void combine_kernel()
{
    int bh = blockIdx.y;
    int t = blockIdx.x * 8 + (threadIdx.x >> 5);
    int fp = threadIdx.x & 31;
    int b = bh >> 3, h = bh & 7;
    float l[NHASH];
    #pragma unroll
    for (int r = 0; r < NHASH; r++) l[r] = g_logits[(bh*NHASH + r)*NN + t];
    float m = fmaxf(fmaxf(l[0], l[1]), fmaxf(l[2], l[3]));
    float s = 0.f;
    #pragma unroll
    for (int r = 0; r < NHASH; r++) s += expf(l[r] - m);
    ull acc = 0ull;
    #pragma unroll
    for (int r = 0; r < NHASH; r++) {
        float wr = expf(l[r] - m) / s;
        ull wd = pack2(wr, wr);
        ull vv = *(const ull*)&g_o[(((size_t)(bh*NHASH + r))*NN + t)*DHD + fp*2];
        fma2(acc, wd, vv);
    }
    *(ull*)&g_att[((size_t)(b*NN + t))*DD + h*DHD + fp*2] = acc;
}

// ---------------- launch ----------------------------------------------------
extern "C" void kernel_launch(void* const* d_in, const int* in_sizes, int n_in,
                              void* d_out, int out_size)
{
    (void)in_sizes; (void)n_in; (void)out_size;
    const float* queries = (const float*)d_in[0];
    // d_in[1] keys, d_in[2] values, d_in[8] attn_mask: unused by ReformerLayer
    const float* Wqk  = (const float*)d_in[3];
    const float* Wv   = (const float*)d_in[4];
    const float* Wout = (const float*)d_in[5];
    const float* bout = (const float*)d_in[6];
    const float* rot  = (const float*)d_in[7];
    float* out = (float*)d_out;

    float *qk, *v, *att;
    cudaGetSymbolAddress((void**)&qk,  g_qk);
    cudaGetSymbolAddress((void**)&v,   g_v);
    cudaGetSymbolAddress((void**)&att, g_att);

    dim3 ggrid(DD/128, MTOT/128);   // (4, 64) = 256 blocks
    // Order chosen so the ncu sample position (launch #3) lands on a GEMM.
    sgemm128<false><<<ggrid, 256>>>(queries, Wqk, nullptr, qk, MTOT, DD, DD);
    hash_kernel<<<dim3(NN/64, BHN), 128>>>(rot);
    sort_kernel<<<BHN*NHASH, 256>>>();
    sgemm128<false><<<ggrid, 256>>>(queries, Wv,  nullptr, v,  MTOT, DD, DD);
    attn_kernel<<<(BHN*CHTOT)/4, 128>>>();
    combine_kernel<<<dim3(NN/8, BHN), 256>>>();
    sgemm128<true><<<ggrid, 256>>>(att, Wout, bout, out, MTOT, DD, DD);
}